// round 12
// baseline (speedup 1.0000x reference)
#include <cuda_runtime.h>

#define Bv 8
#define Sv 100
#define Tv 1200
#define NMELv 80
#define DMv 128
#define KKv 9

typedef unsigned long long u64;

// Scratch (no cudaMalloc allowed)
__device__ float g_x[Bv * Tv * NMELv];          // conv output
__device__ float g_xg[Bv * Tv * 768];           // GRU input projections
__device__ int   g_start[Bv * Sv];              // segment starts (prefix sums)
__device__ int   g_sorted[Bv * Sv];             // chain ids sorted by duration desc
__device__ int   g_items[256];                  // (start<<8)|nc, duration-balanced widths
__device__ int   g_nitems;
__device__ int   g_ctr[2];                      // steal counters (per dir)

__device__ __forceinline__ float sigmoidf_fast(float x) {
    return __fdividef(1.f, 1.f + __expf(-x));
}
__device__ __forceinline__ float tanhf_fast(float x) {
    return 1.f - __fdividef(2.f, __expf(2.f * x) + 1.f);
}

// ---- packed f32x2 helpers (Blackwell sm_103a) ----
__device__ __forceinline__ u64 pk2(float lo, float hi) {
    u64 r; asm("mov.b64 %0, {%1, %2};" : "=l"(r) : "f"(lo), "f"(hi)); return r;
}
__device__ __forceinline__ void up2(u64 v, float& lo, float& hi) {
    asm("mov.b64 {%0, %1}, %2;" : "=f"(lo), "=f"(hi) : "l"(v));
}
__device__ __forceinline__ u64 fma2(u64 a, u64 b, u64 c) {
    u64 d; asm("fma.rn.f32x2 %0, %1, %2, %3;" : "=l"(d) : "l"(a), "l"(b), "l"(c)); return d;
}
__device__ __forceinline__ u64 add2(u64 a, u64 b) {
    u64 d; asm("add.rn.f32x2 %0, %1, %2;" : "=l"(d) : "l"(a), "l"(b)); return d;
}

#define PSW 134   // conv partial-row stride in u64 (1072 B, 16B-aligned rows)
#define PWW 130   // proj packed-W row stride in u64 (1040 B, 16B-aligned rows)
#define GWS 136   // gru W row stride (floats); kh-half offset 68 -> conflict-free LDS.128

// ---------------------------------------------------------------------------
// Kernel 0: prep. Prefix scans, desc counting sort, duration-balanced item
// table (width 8..16 so dur*width ~ 96 chain-steps), steal counters = 74.
// ---------------------------------------------------------------------------
__global__ __launch_bounds__(256) void prep_kernel(const int* __restrict__ durations)
{
    int tid = threadIdx.x;
    __shared__ int bcnt[9], boff[9];
    if (tid < 2) g_ctr[tid] = 74;
    if (tid < 9) bcnt[tid] = 0;
    int wid = tid >> 5, lane = tid & 31;
    if (wid < 8) {
        int carry = 0;
        #pragma unroll
        for (int c0 = 0; c0 < 128; c0 += 32) {
            int ss = c0 + lane;
            int d = (ss < Sv) ? durations[wid * Sv + ss] : 0;
            int v = d;
            #pragma unroll
            for (int off = 1; off < 32; off <<= 1) {
                int n = __shfl_up_sync(0xFFFFFFFFu, v, off);
                if (lane >= off) v += n;
            }
            if (ss < Sv) g_start[wid * Sv + ss] = carry + v - d;
            carry += __shfl_sync(0xFFFFFFFFu, v, 31);
        }
    }
    __syncthreads();
    for (int i = tid; i < Bv * Sv; i += 256)
        atomicAdd(&bcnt[12 - durations[i]], 1);
    __syncthreads();
    if (tid == 0) {
        int off = 0;
        for (int q = 0; q < 9; q++) { boff[q] = off; off += bcnt[q]; }
    }
    __syncthreads();
    __shared__ int bfill[9];
    if (tid < 9) bfill[tid] = boff[tid];
    __syncthreads();
    for (int i = tid; i < Bv * Sv; i += 256) {
        int pos = atomicAdd(&bfill[12 - durations[i]], 1);
        g_sorted[pos] = i;
    }
    __syncthreads();
    if (tid == 0) {
        int ni = 0;
        for (int q = 0; q < 9; q++) {
            int d = 12 - q, cnt = bcnt[q], pos = boff[q];
            int w = (d >= 11) ? 8 : (d >= 9) ? 10 : (d == 8) ? 12 : (d == 7) ? 14 : 16;
            while (cnt > 0) {
                int take = (cnt < w) ? cnt : w;
                g_items[ni++] = (pos << 8) | take;
                pos += take; cnt -= take;
            }
        }
        g_nitems = ni;
    }
}

// ---------------------------------------------------------------------------
// Kernel 1: fused conv stack (best measured config). Unchanged — control.
// ---------------------------------------------------------------------------
__global__ __launch_bounds__(128, 4) void conv_kernel(
    const float* __restrict__ mel, const int* __restrict__ mel_len,
    const float* __restrict__ w1, const float* __restrict__ g1, const float* __restrict__ be1,
    const float* __restrict__ w2, const float* __restrict__ g2, const float* __restrict__ be2)
{
    int bt = blockIdx.x;
    int b = bt / Tv, t = bt - b * Tv;
    if (t >= mel_len[b]) return;

    extern __shared__ __align__(16) float sm[];
    u64* ps2 = (u64*)sm;
    u64* mp2 = ps2 + 40 * PSW;
    int c = threadIdx.x;

    if (c < 48) {
        float lo = (c >= 4) ? mel[bt * NMELv + c - 4] : 0.f;
        float hi = (c < 44) ? mel[bt * NMELv + c + 36] : 0.f;
        mp2[c] = pk2(lo, hi);
    }

    float sc1c = g1[c] * rsqrtf(1.f + 1e-5f);
    float bb1c = be1[c];
    float s2   = g2[0] * rsqrtf(1.f + 1e-5f);
    u64 w1p[KKv], w2p[KKv];
    #pragma unroll
    for (int k = 0; k < KKv; k++) {
        float a = w1[c * KKv + k] * sc1c;  w1p[k] = pk2(a, a);
        float d = w2[c * KKv + k] * s2;    w2p[k] = pk2(d, d);
    }
    u64 bbp = pk2(bb1c, bb1c);
    __syncthreads();

    u64 Yp[48];
    u64 ring[9];
    #pragma unroll
    for (int j = 0; j < 8; j++) ring[j] = mp2[j];
    #pragma unroll
    for (int m = 0; m < 40; m++) {
        ring[(m + 8) % 9] = mp2[m + 8];
        u64 acc = bbp;
        #pragma unroll
        for (int k = 0; k < KKv; k++) acc = fma2(w1p[k], ring[(m + k) % 9], acc);
        float a, h; up2(acc, a, h);
        Yp[m + 4] = pk2(fmaxf(a, 0.f), fmaxf(h, 0.f));
    }
    #pragma unroll
    for (int j = 0; j < 4; j++) {
        float a, h;
        up2(Yp[40 + j], a, h); Yp[j]      = pk2(0.f, a);
        up2(Yp[4 + j],  a, h); Yp[44 + j] = pk2(h, 0.f);
    }

    #pragma unroll
    for (int m = 0; m < 40; m++) {
        u64 acc = 0ull;
        #pragma unroll
        for (int k = 0; k < KKv; k++) acc = fma2(w2p[k], Yp[m + k], acc);
        ps2[m * PSW + c] = acc;
    }
    __syncthreads();

    if (c < 40) {
        const ulonglong2* row = (const ulonglong2*)(ps2 + c * PSW);
        u64 s0 = 0ull, s1 = 0ull;
        #pragma unroll
        for (int q = 0; q < 32; q++) {
            ulonglong2 v0 = row[2 * q];
            ulonglong2 v1 = row[2 * q + 1];
            s0 = add2(s0, add2(v0.x, v0.y));
            s1 = add2(s1, add2(v1.x, v1.y));
        }
        u64 tot = add2(s0, s1);
        float a, h; up2(tot, a, h);
        float bb2 = be2[0];
        g_x[bt * NMELv + c]      = fmaxf(a + bb2, 0.f);
        g_x[bt * NMELv + c + 40] = fmaxf(h + bb2, 0.f);
    }
}

// ---------------------------------------------------------------------------
// Kernel 2: input projection GEMM (unchanged — control).
// ---------------------------------------------------------------------------
__global__ __launch_bounds__(256) void proj_kernel(
    const int* __restrict__ mel_len,
    const float* __restrict__ w_ih_f, const float* __restrict__ b_ih_f,
    const float* __restrict__ w_ih_b, const float* __restrict__ b_ih_b)
{
    int tid = threadIdx.x;
    int b   = blockIdx.z;
    int f0l = blockIdx.x * 64;
    int g0  = blockIdx.y * 128;

    if (f0l >= mel_len[b]) return;

    extern __shared__ __align__(16) char smc[];
    u64*   Ws2 = (u64*)smc;                  // [80][PWW]
    float* Xs  = (float*)(Ws2 + 80 * PWW);   // [80][66]

    for (int i = tid; i < 64 * NMELv; i += 256) {
        int r = i / NMELv, m = i - r * NMELv;
        int fr = min(f0l + r, Tv - 1);
        Xs[m * 66 + r] = g_x[(b * Tv + fr) * NMELv + m];
    }
    const float* wsrc = (g0 < 384) ? (w_ih_f + g0 * NMELv) : (w_ih_b + (g0 - 384) * NMELv);
    const float* bsrc = (g0 < 384) ? (b_ih_f + g0) : (b_ih_b + (g0 - 384));
    for (int i = tid; i < 128 * NMELv; i += 256) {
        int cc = i / NMELv, m = i - cc * NMELv;
        float v = wsrc[i];
        Ws2[m * PWW + cc] = pk2(v, v);
    }
    __syncthreads();

    int tx = tid & 15, ty = tid >> 4;
    u64 acc[8][2];
    #pragma unroll
    for (int u = 0; u < 8; u++) { acc[u][0] = 0ull; acc[u][1] = 0ull; }

    #pragma unroll 4
    for (int m = 0; m < NMELv; m++) {
        u64 x0 = *(const u64*)&Xs[m * 66 + ty * 4];
        u64 x1 = *(const u64*)&Xs[m * 66 + ty * 4 + 2];
        #pragma unroll
        for (int u = 0; u < 8; u++) {
            u64 wp = Ws2[m * PWW + tx + 16 * u];
            acc[u][0] = fma2(wp, x0, acc[u][0]);
            acc[u][1] = fma2(wp, x1, acc[u][1]);
        }
    }
    #pragma unroll
    for (int u = 0; u < 8; u++) {
        int cc = tx + 16 * u;
        float bias = bsrc[cc];
        float a[4];
        up2(acc[u][0], a[0], a[1]);
        up2(acc[u][1], a[2], a[3]);
        #pragma unroll
        for (int v = 0; v < 4; v++) {
            int rr = ty * 4 + v;
            if (f0l + rr < Tv)
                g_xg[(b * Tv + f0l + rr) * 768 + g0 + cc] = a[v] + bias;
        }
    }
}

// ---------------------------------------------------------------------------
// Kernel 3: segment GRU v11 — one variable-width group per block.
// 256 threads; lane = 2*(g%16)+kh (kh = k-half). Thread (g,kh) accumulates
// k in [64kh, 64kh+64) for all 2*NP chain slots; halves exchange via shfl.xor.
// W in smem (stride GWS=136, kh offset 68: conflict-free LDS.128).
// ---------------------------------------------------------------------------
template<int NP>
__device__ __forceinline__ void do_item(
    int start, int nc, int dir, int g, int kh,
    const float* wr, const float* wz, const float* wn,
    float br, float bz, float bn,
    float* hb,
    const int* __restrict__ durations, const int* __restrict__ src_len,
    float* __restrict__ out)
{
    int du[NP]; float hold[NP]; const float* pb[NP]; int eid[NP];
    int mybase = kh * NP;
    int otbase = NP - mybase;
    #pragma unroll
    for (int j = 0; j < NP; j++) {
        int sl = mybase + j;
        int idx = start + min(sl, nc - 1);
        int e = g_sorted[idx];
        eid[j] = (sl < nc) ? e : -1;
        int d = durations[e];
        du[j] = d;
        int sst = g_start[e];
        int b = e / Sv;
        int t0 = dir ? (sst + d - 1) : sst;
        pb[j] = g_xg + dir * 384 + (size_t)(b * Tv + t0) * 768;
        hold[j] = 0.f;
        hb[sl * 128 + g] = 0.f;     // zero buffer 0 slots
    }
    int maxd = durations[g_sorted[start]];
    int kof = 64 * kh;
    int dstep = dir ? -768 : 768;
    __syncthreads();

    for (int i = 0; i < maxd; i++) {
        const float* hcur = hb + (i & 1) * 2048;
        float* hnxt = hb + ((i + 1) & 1) * 2048;
        float xr[NP], xz[NP], xn[NP];
        #pragma unroll
        for (int j = 0; j < NP; j++) {
            xr[j] = pb[j][g]; xz[j] = pb[j][128 + g]; xn[j] = pb[j][256 + g];
        }
        u64 ar[2 * NP], az[2 * NP], an[2 * NP];
        #pragma unroll
        for (int s = 0; s < 2 * NP; s++) { ar[s] = 0ull; az[s] = 0ull; an[s] = 0ull; }
        #pragma unroll 2
        for (int k4 = 0; k4 < 16; k4++) {
            ulonglong2 wrp = *(const ulonglong2*)(wr + 4 * k4);
            ulonglong2 wzp = *(const ulonglong2*)(wz + 4 * k4);
            ulonglong2 wnp = *(const ulonglong2*)(wn + 4 * k4);
            #pragma unroll
            for (int s = 0; s < 2 * NP; s++) {
                ulonglong2 hp = *(const ulonglong2*)(hcur + s * 128 + kof + 4 * k4);
                ar[s] = fma2(wrp.x, hp.x, ar[s]);
                ar[s] = fma2(wrp.y, hp.y, ar[s]);
                az[s] = fma2(wzp.x, hp.x, az[s]);
                az[s] = fma2(wzp.y, hp.y, az[s]);
                an[s] = fma2(wnp.x, hp.x, an[s]);
                an[s] = fma2(wnp.y, hp.y, an[s]);
            }
        }
        #pragma unroll
        for (int j = 0; j < NP; j++) {
            u64 ro = __shfl_xor_sync(0xFFFFFFFFu, ar[otbase + j], 1);
            u64 zo = __shfl_xor_sync(0xFFFFFFFFu, az[otbase + j], 1);
            u64 no = __shfl_xor_sync(0xFFFFFFFFu, an[otbase + j], 1);
            float a0, a1;
            u64 tt = add2(ar[mybase + j], ro); up2(tt, a0, a1);
            float sr = xr[j] + br + a0 + a1;
            tt = add2(az[mybase + j], zo); up2(tt, a0, a1);
            float sz = xz[j] + bz + a0 + a1;
            tt = add2(an[mybase + j], no); up2(tt, a0, a1);
            float sn = bn + a0 + a1;
            float rg = sigmoidf_fast(sr);
            float zg = sigmoidf_fast(sz);
            float nv = tanhf_fast(fmaf(rg, sn, xn[j]));
            float hv = fmaf(zg, hold[j] - nv, nv);     // (1-z)*n + z*h
            if (i < du[j]) hold[j] = hv;               // freeze after segment end
            hnxt[(mybase + j) * 128 + g] = hold[j];
            if (i + 1 < du[j]) pb[j] += dstep;
        }
        __syncthreads();
    }

    #pragma unroll
    for (int j = 0; j < NP; j++) {
        int e = eid[j];
        if (e >= 0) {
            int bb = e / Sv, ss = e - bb * Sv;
            float v = (ss < src_len[bb]) ? hold[j] : 0.f;
            out[e * 256 + dir * 128 + g] = v;
        }
    }
}

__global__ void __launch_bounds__(256) gru_kernel(
    const int* __restrict__ durations, const int* __restrict__ src_len,
    const float* __restrict__ w_hh_f, const float* __restrict__ b_hh_f,
    const float* __restrict__ w_hh_b, const float* __restrict__ b_hh_b,
    float* __restrict__ out)
{
    int dir = blockIdx.x & 1;
    int tid = threadIdx.x;
    int lane = tid & 31, warp = tid >> 5;
    int g = (warp << 4) | (lane >> 1);     // hidden unit 0..127
    int kh = lane & 1;                     // k-half

    extern __shared__ __align__(16) float smg[];
    float* Wt = smg;                       // [384][GWS], kh halves at +0 / +68
    float* hb = Wt + 384 * GWS;            // 2 x [16][128]
    int* itemS = (int*)(hb + 2 * 2048);

    // Load W once: floats [0..63] -> +0, [64..127] -> +68 within each row
    const float* whh = dir ? w_hh_b : w_hh_f;
    {
        const float4* src = (const float4*)whh;
        for (int i = tid; i < 384 * 32; i += 256) {
            int row = i >> 5, q = i & 31;
            int dst = row * GWS + ((q < 16) ? 4 * q : 4 * q + 4);
            *(float4*)&Wt[dst] = src[i];
        }
    }
    __syncthreads();

    const float* bhh = dir ? b_hh_b : b_hh_f;
    float br = bhh[g], bz = bhh[128 + g], bn = bhh[256 + g];
    int kq = 68 * kh;
    const float* wr = Wt + g * GWS + kq;
    const float* wz = Wt + (128 + g) * GWS + kq;
    const float* wn = Wt + (256 + g) * GWS + kq;

    int n_items = g_nitems;
    int item = blockIdx.x >> 1;

    while (item < n_items) {
        int info = g_items[item];
        int start = info >> 8, nc = info & 255;
        int np = (nc + 1) >> 1;
        if (np <= 4)
            do_item<4>(start, nc, dir, g, kh, wr, wz, wn, br, bz, bn, hb, durations, src_len, out);
        else if (np == 5)
            do_item<5>(start, nc, dir, g, kh, wr, wz, wn, br, bz, bn, hb, durations, src_len, out);
        else if (np == 6)
            do_item<6>(start, nc, dir, g, kh, wr, wz, wn, br, bz, bn, hb, durations, src_len, out);
        else if (np == 7)
            do_item<7>(start, nc, dir, g, kh, wr, wz, wn, br, bz, bn, hb, durations, src_len, out);
        else
            do_item<8>(start, nc, dir, g, kh, wr, wz, wn, br, bz, bn, hb, durations, src_len, out);
        __syncthreads();
        if (tid == 0) itemS[0] = atomicAdd(&g_ctr[dir], 1);
        __syncthreads();
        item = itemS[0];
    }
}

// ---------------------------------------------------------------------------
extern "C" void kernel_launch(void* const* d_in, const int* in_sizes, int n_in,
                              void* d_out, int out_size) {
    const float* mel      = (const float*)d_in[0];
    const int*   durations= (const int*)d_in[1];
    const int*   mel_len  = (const int*)d_in[2];
    const int*   src_len  = (const int*)d_in[3];
    const float* w1       = (const float*)d_in[4];
    const float* g1       = (const float*)d_in[5];
    const float* be1      = (const float*)d_in[6];
    const float* w2       = (const float*)d_in[7];
    const float* g2       = (const float*)d_in[8];
    const float* be2      = (const float*)d_in[9];
    const float* w_ih_f   = (const float*)d_in[10];
    const float* w_hh_f   = (const float*)d_in[11];
    const float* b_ih_f   = (const float*)d_in[12];
    const float* b_hh_f   = (const float*)d_in[13];
    const float* w_ih_b   = (const float*)d_in[14];
    const float* w_hh_b   = (const float*)d_in[15];
    const float* b_ih_b   = (const float*)d_in[16];
    const float* b_hh_b   = (const float*)d_in[17];
    float* out = (float*)d_out;

    size_t conv_smem = (size_t)(40 * PSW + 48) * sizeof(u64);
    size_t proj_smem = (size_t)(80 * PWW) * sizeof(u64) + (size_t)(80 * 66) * sizeof(float);
    size_t gru_smem  = (size_t)(384 * GWS + 2 * 2048) * sizeof(float) + 16;
    cudaFuncSetAttribute(conv_kernel, cudaFuncAttributeMaxDynamicSharedMemorySize, (int)conv_smem);
    cudaFuncSetAttribute(proj_kernel, cudaFuncAttributeMaxDynamicSharedMemorySize, (int)proj_smem);
    cudaFuncSetAttribute(gru_kernel,  cudaFuncAttributeMaxDynamicSharedMemorySize, (int)gru_smem);

    prep_kernel<<<1, 256>>>(durations);
    conv_kernel<<<Bv * Tv, 128, conv_smem>>>(mel, mel_len, w1, g1, be1, w2, g2, be2);
    proj_kernel<<<dim3(19, 6, 8), 256, proj_smem>>>(mel_len, w_ih_f, b_ih_f, w_ih_b, b_ih_b);
    gru_kernel<<<148, 256, gru_smem>>>(durations, src_len, w_hh_f, b_hh_f, w_hh_b, b_hh_b, out);
}

// round 13
// speedup vs baseline: 1.4665x; 1.4665x over previous
#include <cuda_runtime.h>

#define Bv 8
#define Sv 100
#define Tv 1200
#define NMELv 80
#define DMv 128
#define KKv 9

typedef unsigned long long u64;

// Scratch (no cudaMalloc allowed)
__device__ float g_x[Bv * Tv * NMELv];          // conv output
__device__ float g_xg[Bv * Tv * 768];           // GRU input projections
__device__ int   g_start[Bv * Sv];              // segment starts (prefix sums)
__device__ int   g_sorted[Bv * Sv];             // chain ids sorted by duration desc
__device__ int   g_ctr[2];                      // steal counters (per dir)

__device__ __forceinline__ float sigmoidf_fast(float x) {
    return __fdividef(1.f, 1.f + __expf(-x));
}
__device__ __forceinline__ float tanhf_fast(float x) {
    return 1.f - __fdividef(2.f, __expf(2.f * x) + 1.f);
}

// ---- packed f32x2 helpers (Blackwell sm_103a) ----
__device__ __forceinline__ u64 pk2(float lo, float hi) {
    u64 r; asm("mov.b64 %0, {%1, %2};" : "=l"(r) : "f"(lo), "f"(hi)); return r;
}
__device__ __forceinline__ void up2(u64 v, float& lo, float& hi) {
    asm("mov.b64 {%0, %1}, %2;" : "=f"(lo), "=f"(hi) : "l"(v));
}
__device__ __forceinline__ u64 fma2(u64 a, u64 b, u64 c) {
    u64 d; asm("fma.rn.f32x2 %0, %1, %2, %3;" : "=l"(d) : "l"(a), "l"(b), "l"(c)); return d;
}
__device__ __forceinline__ u64 add2(u64 a, u64 b) {
    u64 d; asm("add.rn.f32x2 %0, %1, %2;" : "=l"(d) : "l"(a), "l"(b)); return d;
}

#define PSW 134   // conv partial-row stride in u64 (1072 B, 16B-aligned rows)
#define WSW 132   // gru W row stride in floats (528 B, 16B-aligned rows)
#define PWW 130   // proj packed-W row stride in u64 (1040 B, 16B-aligned rows)
#define PXW 68    // proj X row stride in floats (272 B, 16B-aligned rows)

#define NITEMS_T 200   // 4-chain items (800 sorted chains / 4)
#define NSTATIC  148   // items assigned statically; rest stolen

// ---------------------------------------------------------------------------
// Kernel 0: prep. Prefix scans -> g_start; counting sort desc -> g_sorted;
// steal counters start at NSTATIC.
// ---------------------------------------------------------------------------
__global__ __launch_bounds__(256) void prep_kernel(const int* __restrict__ durations)
{
    int tid = threadIdx.x;
    __shared__ int bcnt[9], boff[9];
    if (tid < 2) g_ctr[tid] = NSTATIC;
    if (tid < 9) bcnt[tid] = 0;
    int wid = tid >> 5, lane = tid & 31;
    if (wid < 8) {
        int carry = 0;
        #pragma unroll
        for (int c0 = 0; c0 < 128; c0 += 32) {
            int ss = c0 + lane;
            int d = (ss < Sv) ? durations[wid * Sv + ss] : 0;
            int v = d;
            #pragma unroll
            for (int off = 1; off < 32; off <<= 1) {
                int n = __shfl_up_sync(0xFFFFFFFFu, v, off);
                if (lane >= off) v += n;
            }
            if (ss < Sv) g_start[wid * Sv + ss] = carry + v - d;
            carry += __shfl_sync(0xFFFFFFFFu, v, 31);
        }
    }
    __syncthreads();
    for (int i = tid; i < Bv * Sv; i += 256)
        atomicAdd(&bcnt[12 - durations[i]], 1);
    __syncthreads();
    if (tid == 0) {
        int off = 0;
        for (int q = 0; q < 9; q++) { boff[q] = off; off += bcnt[q]; }
    }
    __syncthreads();
    for (int i = tid; i < Bv * Sv; i += 256) {
        int pos = atomicAdd(&boff[12 - durations[i]], 1);
        g_sorted[pos] = i;
    }
}

// ---------------------------------------------------------------------------
// Kernel 1: fused conv stack (best measured config). Unchanged — control.
// ---------------------------------------------------------------------------
__global__ __launch_bounds__(128, 4) void conv_kernel(
    const float* __restrict__ mel, const int* __restrict__ mel_len,
    const float* __restrict__ w1, const float* __restrict__ g1, const float* __restrict__ be1,
    const float* __restrict__ w2, const float* __restrict__ g2, const float* __restrict__ be2)
{
    int bt = blockIdx.x;
    int b = bt / Tv, t = bt - b * Tv;
    if (t >= mel_len[b]) return;

    extern __shared__ __align__(16) float sm[];
    u64* ps2 = (u64*)sm;                   // [40][PSW] packed partials
    u64* mp2 = ps2 + 40 * PSW;             // 48 packed mel pairs
    int c = threadIdx.x;

    if (c < 48) {
        float lo = (c >= 4) ? mel[bt * NMELv + c - 4] : 0.f;
        float hi = (c < 44) ? mel[bt * NMELv + c + 36] : 0.f;
        mp2[c] = pk2(lo, hi);
    }

    float sc1c = g1[c] * rsqrtf(1.f + 1e-5f);
    float bb1c = be1[c];
    float s2   = g2[0] * rsqrtf(1.f + 1e-5f);
    u64 w1p[KKv], w2p[KKv];
    #pragma unroll
    for (int k = 0; k < KKv; k++) {
        float a = w1[c * KKv + k] * sc1c;  w1p[k] = pk2(a, a);
        float d = w2[c * KKv + k] * s2;    w2p[k] = pk2(d, d);
    }
    u64 bbp = pk2(bb1c, bb1c);
    __syncthreads();

    u64 Yp[48];
    u64 ring[9];
    #pragma unroll
    for (int j = 0; j < 8; j++) ring[j] = mp2[j];
    #pragma unroll
    for (int m = 0; m < 40; m++) {
        ring[(m + 8) % 9] = mp2[m + 8];
        u64 acc = bbp;
        #pragma unroll
        for (int k = 0; k < KKv; k++) acc = fma2(w1p[k], ring[(m + k) % 9], acc);
        float a, h; up2(acc, a, h);
        Yp[m + 4] = pk2(fmaxf(a, 0.f), fmaxf(h, 0.f));
    }
    #pragma unroll
    for (int j = 0; j < 4; j++) {
        float a, h;
        up2(Yp[40 + j], a, h); Yp[j]      = pk2(0.f, a);
        up2(Yp[4 + j],  a, h); Yp[44 + j] = pk2(h, 0.f);
    }

    #pragma unroll
    for (int m = 0; m < 40; m++) {
        u64 acc = 0ull;
        #pragma unroll
        for (int k = 0; k < KKv; k++) acc = fma2(w2p[k], Yp[m + k], acc);
        ps2[m * PSW + c] = acc;
    }
    __syncthreads();

    if (c < 40) {
        const ulonglong2* row = (const ulonglong2*)(ps2 + c * PSW);
        u64 s0 = 0ull, s1 = 0ull;
        #pragma unroll
        for (int q = 0; q < 32; q++) {
            ulonglong2 v0 = row[2 * q];
            ulonglong2 v1 = row[2 * q + 1];
            s0 = add2(s0, add2(v0.x, v0.y));
            s1 = add2(s1, add2(v1.x, v1.y));
        }
        u64 tot = add2(s0, s1);
        float a, h; up2(tot, a, h);
        float bb2 = be2[0];
        g_x[bt * NMELv + c]      = fmaxf(a + bb2, 0.f);
        g_x[bt * NMELv + c + 40] = fmaxf(h + bb2, 0.f);
    }
}

// ---------------------------------------------------------------------------
// Kernel 2: input projection GEMM — vectorized loads.
// Thread tx handles gate PAIRS (2tx+32u, 2tx+32u+1), u = 0..3 -> one LDS.128
// per u for weights; both frame-pairs via one LDS.128 (Xs stride 68 = 16B-aligned).
// ---------------------------------------------------------------------------
__global__ __launch_bounds__(256) void proj_kernel(
    const int* __restrict__ mel_len,
    const float* __restrict__ w_ih_f, const float* __restrict__ b_ih_f,
    const float* __restrict__ w_ih_b, const float* __restrict__ b_ih_b)
{
    int tid = threadIdx.x;
    int b   = blockIdx.z;
    int f0l = blockIdx.x * 64;
    int g0  = blockIdx.y * 128;

    if (f0l >= mel_len[b]) return;

    extern __shared__ __align__(16) char smc[];
    u64*   Ws2 = (u64*)smc;                  // [80][PWW] duplicated pairs
    float* Xs  = (float*)(Ws2 + 80 * PWW);   // [80][PXW]

    for (int i = tid; i < 64 * NMELv; i += 256) {
        int r = i / NMELv, m = i - r * NMELv;
        int fr = min(f0l + r, Tv - 1);
        Xs[m * PXW + r] = g_x[(b * Tv + fr) * NMELv + m];
    }
    const float* wsrc = (g0 < 384) ? (w_ih_f + g0 * NMELv) : (w_ih_b + (g0 - 384) * NMELv);
    const float* bsrc = (g0 < 384) ? (b_ih_f + g0) : (b_ih_b + (g0 - 384));
    for (int i = tid; i < 128 * NMELv; i += 256) {
        int cc = i / NMELv, m = i - cc * NMELv;   // coalesced LDG
        float v = wsrc[i];
        Ws2[m * PWW + cc] = pk2(v, v);
    }
    __syncthreads();

    int tx = tid & 15, ty = tid >> 4;
    u64 acc[4][2][2];   // [u][gate-in-pair][frame-pair]
    #pragma unroll
    for (int u = 0; u < 4; u++)
        #pragma unroll
        for (int p = 0; p < 2; p++) { acc[u][p][0] = 0ull; acc[u][p][1] = 0ull; }

    #pragma unroll 4
    for (int m = 0; m < NMELv; m++) {
        ulonglong2 xp = *(const ulonglong2*)&Xs[m * PXW + ty * 4];   // frames f..f+3
        #pragma unroll
        for (int u = 0; u < 4; u++) {
            ulonglong2 wp = *(const ulonglong2*)&Ws2[m * PWW + 2 * tx + 32 * u];
            acc[u][0][0] = fma2(wp.x, xp.x, acc[u][0][0]);
            acc[u][0][1] = fma2(wp.x, xp.y, acc[u][0][1]);
            acc[u][1][0] = fma2(wp.y, xp.x, acc[u][1][0]);
            acc[u][1][1] = fma2(wp.y, xp.y, acc[u][1][1]);
        }
    }
    #pragma unroll
    for (int u = 0; u < 4; u++) {
        #pragma unroll
        for (int p = 0; p < 2; p++) {
            int cc = 2 * tx + 32 * u + p;
            float bias = bsrc[cc];
            float a[4];
            up2(acc[u][p][0], a[0], a[1]);
            up2(acc[u][p][1], a[2], a[3]);
            #pragma unroll
            for (int v = 0; v < 4; v++) {
                int rr = ty * 4 + v;
                if (f0l + rr < Tv)
                    g_xg[(b * Tv + f0l + rr) * 768 + g0 + cc] = a[v] + bias;
            }
        }
    }
}

// ---------------------------------------------------------------------------
// Kernel 3: segment GRU v10 (round-11 verbatim — profiled 47.8us, regs=140).
// 4-chain LPT items, static long-short pairing + stealing, double-buffered h
// (ONE barrier per step), 12 u64 accumulators.
// ---------------------------------------------------------------------------
__global__ void __launch_bounds__(256, 1) gru_kernel(
    const int* __restrict__ durations, const int* __restrict__ src_len,
    const float* __restrict__ w_hh_f, const float* __restrict__ b_hh_f,
    const float* __restrict__ w_hh_b, const float* __restrict__ b_hh_b,
    float* __restrict__ out)
{
    int dir = blockIdx.x & 1;
    int rank = blockIdx.x >> 1;        // 0..73 per dir
    int tid = threadIdx.x;
    int half = tid >> 7;
    int g = tid & 127;                 // hidden unit
    int barid = 1 + half;

    extern __shared__ __align__(16) float smg[];
    float* Wt = smg;                        // [384][WSW]
    float* hs = Wt + 384 * WSW;             // [2 stealers][2 buf][4 cb][128]
    int* itemS = (int*)(hs + 2 * 2 * 4 * 128);

    // Load W once (all 256 threads)
    const float* whh = dir ? w_hh_b : w_hh_f;
    {
        const float4* src = (const float4*)whh;
        for (int i = tid; i < 384 * 32; i += 256) {
            int row = i >> 5, q = i & 31;
            *(float4*)&Wt[row * WSW + 4 * q] = src[i];
        }
    }
    __syncthreads();

    const float* bhh = dir ? b_hh_b : b_hh_f;
    float br = bhh[g], bz = bhh[128 + g], bn = bhh[256 + g];
    const float* wr = Wt + g * WSW;
    const float* wz = Wt + (128 + g) * WSW;
    const float* wn = Wt + (256 + g) * WSW;
    const float* xbase = g_xg + dir * 384;
    float* hbuf = hs + half * 1024;    // [2][4][128]

    // Static LPT assignment: half0 -> rank (longest spread), half1 -> 147-rank
    int item = half ? (147 - rank) : rank;

    while (item < NITEMS_T) {
        int ee[4], st[4], du[4], bt4[4];
        int maxd = 0;
        #pragma unroll
        for (int cb = 0; cb < 4; cb++) {
            int e = g_sorted[item * 4 + cb];
            ee[cb] = e;
            st[cb] = g_start[e];
            du[cb] = durations[e];
            bt4[cb] = (e / Sv) * Tv;
            maxd = max(maxd, du[cb]);
        }
        float hold[4] = {0.f, 0.f, 0.f, 0.f};
        #pragma unroll
        for (int cb = 0; cb < 4; cb++) hbuf[cb * 128 + g] = 0.f;   // buffer 0
        asm volatile("bar.sync %0, 128;" :: "r"(barid) : "memory");

        for (int i = 0; i < maxd; i++) {
            const float* hcur = hbuf + (i & 1) * 512;
            float* hnxt = hbuf + ((i + 1) & 1) * 512;
            float xr[4], xz[4], xn4[4];
            #pragma unroll
            for (int cb = 0; cb < 4; cb++) {
                int d = du[cb];
                int ie = min(i, d - 1);
                int t = st[cb] + (dir ? (d - 1 - ie) : ie);
                const float* p = xbase + (bt4[cb] + t) * 768;
                xr[cb] = p[g]; xz[cb] = p[128 + g]; xn4[cb] = p[256 + g];
            }
            u64 ar[4], az[4], an[4];
            #pragma unroll
            for (int cb = 0; cb < 4; cb++) { ar[cb] = 0ull; az[cb] = 0ull; an[cb] = 0ull; }
            #pragma unroll 4
            for (int k4 = 0; k4 < 32; k4++) {
                ulonglong2 wrp = *(const ulonglong2*)(wr + 4 * k4);
                ulonglong2 wzp = *(const ulonglong2*)(wz + 4 * k4);
                ulonglong2 wnp = *(const ulonglong2*)(wn + 4 * k4);
                #pragma unroll
                for (int cb = 0; cb < 4; cb++) {
                    ulonglong2 hp = *(const ulonglong2*)(hcur + cb * 128 + 4 * k4);
                    ar[cb] = fma2(wrp.x, hp.x, ar[cb]);
                    ar[cb] = fma2(wrp.y, hp.y, ar[cb]);
                    az[cb] = fma2(wzp.x, hp.x, az[cb]);
                    az[cb] = fma2(wzp.y, hp.y, az[cb]);
                    an[cb] = fma2(wnp.x, hp.x, an[cb]);
                    an[cb] = fma2(wnp.y, hp.y, an[cb]);
                }
            }
            #pragma unroll
            for (int cb = 0; cb < 4; cb++) {
                float e0, e1;
                up2(ar[cb], e0, e1);
                float rr = sigmoidf_fast(xr[cb] + br + e0 + e1);
                up2(az[cb], e0, e1);
                float zz = sigmoidf_fast(xz[cb] + bz + e0 + e1);
                up2(an[cb], e0, e1);
                float nv = tanhf_fast(fmaf(rr, bn + e0 + e1, xn4[cb]));
                float hv = fmaf(zz, hold[cb] - nv, nv);     // (1-z)*n + z*h
                if (i < du[cb]) hold[cb] = hv;              // freeze after segment end
                hnxt[cb * 128 + g] = hold[cb];
            }
            asm volatile("bar.sync %0, 128;" :: "r"(barid) : "memory"); // ONE bar/step
        }

        #pragma unroll
        for (int cb = 0; cb < 4; cb++) {
            int e = ee[cb];
            int bb = e / Sv, ss = e - bb * Sv;
            float v = (ss < src_len[bb]) ? hold[cb] : 0.f;
            out[e * 256 + dir * 128 + g] = v;
        }

        // steal next item
        if (g == 0) itemS[half] = atomicAdd(&g_ctr[dir], 1);
        asm volatile("bar.sync %0, 128;" :: "r"(barid) : "memory");
        item = itemS[half];
    }
}

// ---------------------------------------------------------------------------
extern "C" void kernel_launch(void* const* d_in, const int* in_sizes, int n_in,
                              void* d_out, int out_size) {
    const float* mel      = (const float*)d_in[0];
    const int*   durations= (const int*)d_in[1];
    const int*   mel_len  = (const int*)d_in[2];
    const int*   src_len  = (const int*)d_in[3];
    const float* w1       = (const float*)d_in[4];
    const float* g1       = (const float*)d_in[5];
    const float* be1      = (const float*)d_in[6];
    const float* w2       = (const float*)d_in[7];
    const float* g2       = (const float*)d_in[8];
    const float* be2      = (const float*)d_in[9];
    const float* w_ih_f   = (const float*)d_in[10];
    const float* w_hh_f   = (const float*)d_in[11];
    const float* b_ih_f   = (const float*)d_in[12];
    const float* b_hh_f   = (const float*)d_in[13];
    const float* w_ih_b   = (const float*)d_in[14];
    const float* w_hh_b   = (const float*)d_in[15];
    const float* b_ih_b   = (const float*)d_in[16];
    const float* b_hh_b   = (const float*)d_in[17];
    float* out = (float*)d_out;

    size_t conv_smem = (size_t)(40 * PSW + 48) * sizeof(u64);
    size_t proj_smem = (size_t)(80 * PWW) * sizeof(u64) + (size_t)(80 * PXW) * sizeof(float);
    size_t gru_smem  = (size_t)(384 * WSW + 2 * 2 * 4 * 128) * sizeof(float) + 8;
    cudaFuncSetAttribute(conv_kernel, cudaFuncAttributeMaxDynamicSharedMemorySize, (int)conv_smem);
    cudaFuncSetAttribute(proj_kernel, cudaFuncAttributeMaxDynamicSharedMemorySize, (int)proj_smem);
    cudaFuncSetAttribute(gru_kernel,  cudaFuncAttributeMaxDynamicSharedMemorySize, (int)gru_smem);

    prep_kernel<<<1, 256>>>(durations);
    conv_kernel<<<Bv * Tv, 128, conv_smem>>>(mel, mel_len, w1, g1, be1, w2, g2, be2);
    proj_kernel<<<dim3(19, 6, 8), 256, proj_smem>>>(mel_len, w_ih_f, b_ih_f, w_ih_b, b_ih_b);
    gru_kernel<<<148, 256, gru_smem>>>(durations, src_len, w_hh_f, b_hh_f, w_hh_b, b_hh_b, out);
}

// round 14
// speedup vs baseline: 1.5306x; 1.0437x over previous
#include <cuda_runtime.h>

#define Bv 8
#define Sv 100
#define Tv 1200
#define NMELv 80
#define DMv 128
#define KKv 9

typedef unsigned long long u64;

// Scratch (no cudaMalloc allowed)
__device__ float g_x[Bv * Tv * NMELv];          // conv output
__device__ float g_xg[Bv * Tv * 768];           // GRU input projections
__device__ int   g_start[Bv * Sv];              // segment starts (prefix sums)
__device__ int   g_sorted[Bv * Sv];             // chain ids sorted by duration desc
__device__ int   g_ctr[2];                      // steal counters (per dir)

__device__ __forceinline__ float sigmoidf_fast(float x) {
    return __fdividef(1.f, 1.f + __expf(-x));
}
__device__ __forceinline__ float tanhf_fast(float x) {
    return 1.f - __fdividef(2.f, __expf(2.f * x) + 1.f);
}

// ---- packed f32x2 helpers (Blackwell sm_103a) ----
__device__ __forceinline__ u64 pk2(float lo, float hi) {
    u64 r; asm("mov.b64 %0, {%1, %2};" : "=l"(r) : "f"(lo), "f"(hi)); return r;
}
__device__ __forceinline__ void up2(u64 v, float& lo, float& hi) {
    asm("mov.b64 {%0, %1}, %2;" : "=f"(lo), "=f"(hi) : "l"(v));
}
__device__ __forceinline__ u64 fma2(u64 a, u64 b, u64 c) {
    u64 d; asm("fma.rn.f32x2 %0, %1, %2, %3;" : "=l"(d) : "l"(a), "l"(b), "l"(c)); return d;
}
__device__ __forceinline__ u64 add2(u64 a, u64 b) {
    u64 d; asm("add.rn.f32x2 %0, %1, %2;" : "=l"(d) : "l"(a), "l"(b)); return d;
}

#define PSW 134   // conv partial-row stride in u64 (1072 B, 16B-aligned rows)
#define WSW 132   // gru W row stride in floats (528 B, 16B-aligned rows)
#define PWW 130   // proj packed-W row stride in u64 (1040 B, 16B-aligned rows)

#define NITEMS_T 200   // 4-chain items (800 sorted chains / 4)
#define NSTATIC  148   // items assigned statically; rest stolen

// ---------------------------------------------------------------------------
// Kernel 1: fused conv stack + prep fold-in (block Bv*Tv does prep & exits).
// Conv reduction now uses 120 threads (3 partial sums per output row).
// ---------------------------------------------------------------------------
__global__ __launch_bounds__(128, 4) void conv_kernel(
    const float* __restrict__ mel, const int* __restrict__ mel_len,
    const int* __restrict__ durations,
    const float* __restrict__ w1, const float* __restrict__ g1, const float* __restrict__ be1,
    const float* __restrict__ w2, const float* __restrict__ g2, const float* __restrict__ be2)
{
    int bt = blockIdx.x;
    int c = threadIdx.x;

    // ---- prep block: scans, LPT sort, counter reset ----
    if (bt == Bv * Tv) {
        __shared__ int bcnt[9], boff[9];
        if (c < 2) g_ctr[c] = NSTATIC;
        if (c < 9) bcnt[c] = 0;
        int wid = c >> 5, lane = c & 31;
        if (wid < 4) {
            // 4 warps handle 8 rows: warp w does rows 2w, 2w+1
            for (int rr = 2 * wid; rr < 2 * wid + 2; rr++) {
                int carry = 0;
                #pragma unroll
                for (int c0 = 0; c0 < 128; c0 += 32) {
                    int ss = c0 + lane;
                    int d = (ss < Sv) ? durations[rr * Sv + ss] : 0;
                    int v = d;
                    #pragma unroll
                    for (int off = 1; off < 32; off <<= 1) {
                        int n = __shfl_up_sync(0xFFFFFFFFu, v, off);
                        if (lane >= off) v += n;
                    }
                    if (ss < Sv) g_start[rr * Sv + ss] = carry + v - d;
                    carry += __shfl_sync(0xFFFFFFFFu, v, 31);
                }
            }
        }
        __syncthreads();
        for (int i = c; i < Bv * Sv; i += 128)
            atomicAdd(&bcnt[12 - durations[i]], 1);
        __syncthreads();
        if (c == 0) {
            int off = 0;
            for (int q = 0; q < 9; q++) { boff[q] = off; off += bcnt[q]; }
        }
        __syncthreads();
        for (int i = c; i < Bv * Sv; i += 128) {
            int pos = atomicAdd(&boff[12 - durations[i]], 1);
            g_sorted[pos] = i;
        }
        return;
    }

    int b = bt / Tv, t = bt - b * Tv;
    if (t >= mel_len[b]) return;

    extern __shared__ __align__(16) float sm[];
    u64* ps2 = (u64*)sm;                   // [40][PSW] packed partials
    u64* mp2 = ps2 + 40 * PSW;             // 48 packed mel pairs
    u64* red = mp2 + 48;                   // [40][3] stage-1 partials

    if (c < 48) {
        float lo = (c >= 4) ? mel[bt * NMELv + c - 4] : 0.f;
        float hi = (c < 44) ? mel[bt * NMELv + c + 36] : 0.f;
        mp2[c] = pk2(lo, hi);
    }

    float sc1c = g1[c] * rsqrtf(1.f + 1e-5f);
    float bb1c = be1[c];
    float s2   = g2[0] * rsqrtf(1.f + 1e-5f);
    u64 w1p[KKv], w2p[KKv];
    #pragma unroll
    for (int k = 0; k < KKv; k++) {
        float a = w1[c * KKv + k] * sc1c;  w1p[k] = pk2(a, a);
        float d = w2[c * KKv + k] * s2;    w2p[k] = pk2(d, d);
    }
    u64 bbp = pk2(bb1c, bb1c);
    __syncthreads();

    u64 Yp[48];
    u64 ring[9];
    #pragma unroll
    for (int j = 0; j < 8; j++) ring[j] = mp2[j];
    #pragma unroll
    for (int m = 0; m < 40; m++) {
        ring[(m + 8) % 9] = mp2[m + 8];
        u64 acc = bbp;
        #pragma unroll
        for (int k = 0; k < KKv; k++) acc = fma2(w1p[k], ring[(m + k) % 9], acc);
        float a, h; up2(acc, a, h);
        Yp[m + 4] = pk2(fmaxf(a, 0.f), fmaxf(h, 0.f));
    }
    #pragma unroll
    for (int j = 0; j < 4; j++) {
        float a, h;
        up2(Yp[40 + j], a, h); Yp[j]      = pk2(0.f, a);
        up2(Yp[4 + j],  a, h); Yp[44 + j] = pk2(h, 0.f);
    }

    #pragma unroll
    for (int m = 0; m < 40; m++) {
        u64 acc = 0ull;
        #pragma unroll
        for (int k = 0; k < KKv; k++) acc = fma2(w2p[k], Yp[m + k], acc);
        ps2[m * PSW + c] = acc;
    }
    __syncthreads();

    // Stage 1: 120 threads, 3 partials per output row (c-ranges of ~43)
    if (c < 120) {
        int m = c % 40, part = c / 40;
        int c0 = part * 43;
        int c1 = min(128, c0 + 43);
        const u64* row = ps2 + m * PSW;
        u64 s = 0ull;
        // 16B-aligned chunks
        int cc = c0;
        if (cc & 1) { s = add2(s, row[cc]); cc++; }
        for (; cc + 1 < c1; cc += 2) {
            ulonglong2 v = *(const ulonglong2*)(row + cc);
            s = add2(s, add2(v.x, v.y));
        }
        if (cc < c1) s = add2(s, row[cc]);
        red[m * 3 + part] = s;
    }
    __syncthreads();

    // Stage 2: 40 threads combine 3 partials, write both outputs
    if (c < 40) {
        u64 tot = add2(add2(red[c * 3], red[c * 3 + 1]), red[c * 3 + 2]);
        float a, h; up2(tot, a, h);
        float bb2 = be2[0];
        g_x[bt * NMELv + c]      = fmaxf(a + bb2, 0.f);
        g_x[bt * NMELv + c + 40] = fmaxf(h + bb2, 0.f);
    }
}

// ---------------------------------------------------------------------------
// Kernel 2: input projection GEMM (round-11 verbatim — part of the 138.2
// config; W loads are 128B-contiguous broadcast-friendly LDS.64).
// ---------------------------------------------------------------------------
__global__ __launch_bounds__(256) void proj_kernel(
    const int* __restrict__ mel_len,
    const float* __restrict__ w_ih_f, const float* __restrict__ b_ih_f,
    const float* __restrict__ w_ih_b, const float* __restrict__ b_ih_b)
{
    int tid = threadIdx.x;
    int b   = blockIdx.z;
    int f0l = blockIdx.x * 64;
    int g0  = blockIdx.y * 128;

    if (f0l >= mel_len[b]) return;

    extern __shared__ __align__(16) char smc[];
    u64*   Ws2 = (u64*)smc;                  // [80][PWW] duplicated pairs
    float* Xs  = (float*)(Ws2 + 80 * PWW);   // [80][66]

    for (int i = tid; i < 64 * NMELv; i += 256) {
        int r = i / NMELv, m = i - r * NMELv;
        int fr = min(f0l + r, Tv - 1);
        Xs[m * 66 + r] = g_x[(b * Tv + fr) * NMELv + m];
    }
    const float* wsrc = (g0 < 384) ? (w_ih_f + g0 * NMELv) : (w_ih_b + (g0 - 384) * NMELv);
    const float* bsrc = (g0 < 384) ? (b_ih_f + g0) : (b_ih_b + (g0 - 384));
    for (int i = tid; i < 128 * NMELv; i += 256) {
        int cc = i / NMELv, m = i - cc * NMELv;
        float v = wsrc[i];
        Ws2[m * PWW + cc] = pk2(v, v);
    }
    __syncthreads();

    int tx = tid & 15, ty = tid >> 4;
    u64 acc[8][2];
    #pragma unroll
    for (int u = 0; u < 8; u++) { acc[u][0] = 0ull; acc[u][1] = 0ull; }

    #pragma unroll 4
    for (int m = 0; m < NMELv; m++) {
        u64 x0 = *(const u64*)&Xs[m * 66 + ty * 4];
        u64 x1 = *(const u64*)&Xs[m * 66 + ty * 4 + 2];
        #pragma unroll
        for (int u = 0; u < 8; u++) {
            u64 wp = Ws2[m * PWW + tx + 16 * u];
            acc[u][0] = fma2(wp, x0, acc[u][0]);
            acc[u][1] = fma2(wp, x1, acc[u][1]);
        }
    }
    #pragma unroll
    for (int u = 0; u < 8; u++) {
        int cc = tx + 16 * u;
        float bias = bsrc[cc];
        float a[4];
        up2(acc[u][0], a[0], a[1]);
        up2(acc[u][1], a[2], a[3]);
        #pragma unroll
        for (int v = 0; v < 4; v++) {
            int rr = ty * 4 + v;
            if (f0l + rr < Tv)
                g_xg[(b * Tv + f0l + rr) * 768 + g0 + cc] = a[v] + bias;
        }
    }
}

// ---------------------------------------------------------------------------
// Kernel 3: segment GRU v10 (profiled 47.8-48.2us, regs=140). Unchanged.
// ---------------------------------------------------------------------------
__global__ void __launch_bounds__(256, 1) gru_kernel(
    const int* __restrict__ durations, const int* __restrict__ src_len,
    const float* __restrict__ w_hh_f, const float* __restrict__ b_hh_f,
    const float* __restrict__ w_hh_b, const float* __restrict__ b_hh_b,
    float* __restrict__ out)
{
    int dir = blockIdx.x & 1;
    int rank = blockIdx.x >> 1;        // 0..73 per dir
    int tid = threadIdx.x;
    int half = tid >> 7;
    int g = tid & 127;                 // hidden unit
    int barid = 1 + half;

    extern __shared__ __align__(16) float smg[];
    float* Wt = smg;                        // [384][WSW]
    float* hs = Wt + 384 * WSW;             // [2 stealers][2 buf][4 cb][128]
    int* itemS = (int*)(hs + 2 * 2 * 4 * 128);

    const float* whh = dir ? w_hh_b : w_hh_f;
    {
        const float4* src = (const float4*)whh;
        for (int i = tid; i < 384 * 32; i += 256) {
            int row = i >> 5, q = i & 31;
            *(float4*)&Wt[row * WSW + 4 * q] = src[i];
        }
    }
    __syncthreads();

    const float* bhh = dir ? b_hh_b : b_hh_f;
    float br = bhh[g], bz = bhh[128 + g], bn = bhh[256 + g];
    const float* wr = Wt + g * WSW;
    const float* wz = Wt + (128 + g) * WSW;
    const float* wn = Wt + (256 + g) * WSW;
    const float* xbase = g_xg + dir * 384;
    float* hbuf = hs + half * 1024;    // [2][4][128]

    int item = half ? (147 - rank) : rank;

    while (item < NITEMS_T) {
        int ee[4], st[4], du[4], bt4[4];
        int maxd = 0;
        #pragma unroll
        for (int cb = 0; cb < 4; cb++) {
            int e = g_sorted[item * 4 + cb];
            ee[cb] = e;
            st[cb] = g_start[e];
            du[cb] = durations[e];
            bt4[cb] = (e / Sv) * Tv;
            maxd = max(maxd, du[cb]);
        }
        float hold[4] = {0.f, 0.f, 0.f, 0.f};
        #pragma unroll
        for (int cb = 0; cb < 4; cb++) hbuf[cb * 128 + g] = 0.f;
        asm volatile("bar.sync %0, 128;" :: "r"(barid) : "memory");

        for (int i = 0; i < maxd; i++) {
            const float* hcur = hbuf + (i & 1) * 512;
            float* hnxt = hbuf + ((i + 1) & 1) * 512;
            float xr[4], xz[4], xn4[4];
            #pragma unroll
            for (int cb = 0; cb < 4; cb++) {
                int d = du[cb];
                int ie = min(i, d - 1);
                int t = st[cb] + (dir ? (d - 1 - ie) : ie);
                const float* p = xbase + (bt4[cb] + t) * 768;
                xr[cb] = p[g]; xz[cb] = p[128 + g]; xn4[cb] = p[256 + g];
            }
            u64 ar[4], az[4], an[4];
            #pragma unroll
            for (int cb = 0; cb < 4; cb++) { ar[cb] = 0ull; az[cb] = 0ull; an[cb] = 0ull; }
            #pragma unroll 4
            for (int k4 = 0; k4 < 32; k4++) {
                ulonglong2 wrp = *(const ulonglong2*)(wr + 4 * k4);
                ulonglong2 wzp = *(const ulonglong2*)(wz + 4 * k4);
                ulonglong2 wnp = *(const ulonglong2*)(wn + 4 * k4);
                #pragma unroll
                for (int cb = 0; cb < 4; cb++) {
                    ulonglong2 hp = *(const ulonglong2*)(hcur + cb * 128 + 4 * k4);
                    ar[cb] = fma2(wrp.x, hp.x, ar[cb]);
                    ar[cb] = fma2(wrp.y, hp.y, ar[cb]);
                    az[cb] = fma2(wzp.x, hp.x, az[cb]);
                    az[cb] = fma2(wzp.y, hp.y, az[cb]);
                    an[cb] = fma2(wnp.x, hp.x, an[cb]);
                    an[cb] = fma2(wnp.y, hp.y, an[cb]);
                }
            }
            #pragma unroll
            for (int cb = 0; cb < 4; cb++) {
                float e0, e1;
                up2(ar[cb], e0, e1);
                float rr = sigmoidf_fast(xr[cb] + br + e0 + e1);
                up2(az[cb], e0, e1);
                float zz = sigmoidf_fast(xz[cb] + bz + e0 + e1);
                up2(an[cb], e0, e1);
                float nv = tanhf_fast(fmaf(rr, bn + e0 + e1, xn4[cb]));
                float hv = fmaf(zz, hold[cb] - nv, nv);
                if (i < du[cb]) hold[cb] = hv;
                hnxt[cb * 128 + g] = hold[cb];
            }
            asm volatile("bar.sync %0, 128;" :: "r"(barid) : "memory");
        }

        #pragma unroll
        for (int cb = 0; cb < 4; cb++) {
            int e = ee[cb];
            int bb = e / Sv, ss = e - bb * Sv;
            float v = (ss < src_len[bb]) ? hold[cb] : 0.f;
            out[e * 256 + dir * 128 + g] = v;
        }

        if (g == 0) itemS[half] = atomicAdd(&g_ctr[dir], 1);
        asm volatile("bar.sync %0, 128;" :: "r"(barid) : "memory");
        item = itemS[half];
    }
}

// ---------------------------------------------------------------------------
extern "C" void kernel_launch(void* const* d_in, const int* in_sizes, int n_in,
                              void* d_out, int out_size) {
    const float* mel      = (const float*)d_in[0];
    const int*   durations= (const int*)d_in[1];
    const int*   mel_len  = (const int*)d_in[2];
    const int*   src_len  = (const int*)d_in[3];
    const float* w1       = (const float*)d_in[4];
    const float* g1       = (const float*)d_in[5];
    const float* be1      = (const float*)d_in[6];
    const float* w2       = (const float*)d_in[7];
    const float* g2       = (const float*)d_in[8];
    const float* be2      = (const float*)d_in[9];
    const float* w_ih_f   = (const float*)d_in[10];
    const float* w_hh_f   = (const float*)d_in[11];
    const float* b_ih_f   = (const float*)d_in[12];
    const float* b_hh_f   = (const float*)d_in[13];
    const float* w_ih_b   = (const float*)d_in[14];
    const float* w_hh_b   = (const float*)d_in[15];
    const float* b_ih_b   = (const float*)d_in[16];
    const float* b_hh_b   = (const float*)d_in[17];
    float* out = (float*)d_out;

    size_t conv_smem = (size_t)(40 * PSW + 48 + 120) * sizeof(u64);
    size_t proj_smem = (size_t)(80 * PWW) * sizeof(u64) + (size_t)(80 * 66) * sizeof(float);
    size_t gru_smem  = (size_t)(384 * WSW + 2 * 2 * 4 * 128) * sizeof(float) + 8;
    cudaFuncSetAttribute(conv_kernel, cudaFuncAttributeMaxDynamicSharedMemorySize, (int)conv_smem);
    cudaFuncSetAttribute(proj_kernel, cudaFuncAttributeMaxDynamicSharedMemorySize, (int)proj_smem);
    cudaFuncSetAttribute(gru_kernel,  cudaFuncAttributeMaxDynamicSharedMemorySize, (int)gru_smem);

    conv_kernel<<<Bv * Tv + 1, 128, conv_smem>>>(mel, mel_len, durations,
                                                 w1, g1, be1, w2, g2, be2);
    proj_kernel<<<dim3(19, 6, 8), 256, proj_smem>>>(mel_len, w_ih_f, b_ih_f, w_ih_b, b_ih_b);
    gru_kernel<<<148, 256, gru_smem>>>(durations, src_len, w_hh_f, b_hh_f, w_hh_b, b_hh_b, out);
}